// round 13
// baseline (speedup 1.0000x reference)
#include <cuda_runtime.h>
#include <cuda_fp16.h>
#include <math.h>
#include <stdint.h>

#define D_    2048
#define H_    16
#define KVH_  4
#define HD_   128
#define E_    8
#define I_    1408
#define SI_   5632
#define T_    1024
#define CAP   1024

typedef __half f16;

// ---------------- scratch (device globals; allocation-free) ----------------
__device__ float d_q[T_ * D_];
__device__ float d_k[T_ * KVH_ * HD_];
__device__ float d_v[T_ * KVH_ * HD_];
__device__ float d_h[T_ * D_];
__device__ float d_x2f[T_ * D_];
__device__ float d_g[E_ * CAP * I_];
__device__ float d_u[E_ * CAP * I_];
__device__ float d_moe[2 * T_ * D_];
__device__ float d_shg[T_ * SI_];
__device__ float d_shu[T_ * SI_];
__device__ float d_shd[T_ * D_];
__device__ float d_wslot[T_ * 2];
__device__ float d_sgate[T_];
__device__ int   d_cnt[E_];
__device__ int   d_list[E_ * CAP];
__device__ f16 d_qh[T_ * D_];
__device__ f16 d_kh[T_ * KVH_ * HD_];
__device__ f16 d_vh[T_ * KVH_ * HD_];
__device__ f16 d_xn_h[T_ * D_];
__device__ f16 d_x2_h[T_ * D_];
__device__ f16 d_ao_h[T_ * D_];
__device__ f16 d_ga_h[E_ * CAP * I_];
__device__ f16 d_sa_h[T_ * SI_];

// ---------------- PTX helpers ----------------
__device__ __forceinline__ unsigned sm_u32(const void* p) {
    return (unsigned)__cvta_generic_to_shared(p);
}
__device__ __forceinline__ void cp16(unsigned dst, const void* src) {
    asm volatile("cp.async.cg.shared.global [%0], [%1], 16;\n" :: "r"(dst), "l"(src));
}
__device__ __forceinline__ void cp16z(unsigned dst, const void* src, bool pred) {
    int sz = pred ? 16 : 0;
    asm volatile("cp.async.cg.shared.global [%0], [%1], 16, %2;\n" :: "r"(dst), "l"(src), "r"(sz));
}
__device__ __forceinline__ void cp_commit() { asm volatile("cp.async.commit_group;\n"); }
template<int N> __device__ __forceinline__ void cp_wait() {
    asm volatile("cp.async.wait_group %0;\n" :: "n"(N));
}
__device__ __forceinline__ void ldsm4(unsigned& r0, unsigned& r1, unsigned& r2, unsigned& r3, unsigned a) {
    asm volatile("ldmatrix.sync.aligned.m8n8.x4.shared.b16 {%0,%1,%2,%3}, [%4];\n"
                 : "=r"(r0), "=r"(r1), "=r"(r2), "=r"(r3) : "r"(a));
}
__device__ __forceinline__ void ldsm4t(unsigned& r0, unsigned& r1, unsigned& r2, unsigned& r3, unsigned a) {
    asm volatile("ldmatrix.sync.aligned.m8n8.x4.trans.shared.b16 {%0,%1,%2,%3}, [%4];\n"
                 : "=r"(r0), "=r"(r1), "=r"(r2), "=r"(r3) : "r"(a));
}
__device__ __forceinline__ void ldsm2(unsigned& r0, unsigned& r1, unsigned a) {
    asm volatile("ldmatrix.sync.aligned.m8n8.x2.shared.b16 {%0,%1}, [%2];\n"
                 : "=r"(r0), "=r"(r1) : "r"(a));
}
__device__ __forceinline__ void mma_f16(float* c, const unsigned* a, const unsigned* b) {
    asm volatile("mma.sync.aligned.m16n8k16.row.col.f32.f16.f16.f32 "
                 "{%0,%1,%2,%3}, {%4,%5,%6,%7}, {%8,%9}, {%0,%1,%2,%3};\n"
                 : "+f"(c[0]), "+f"(c[1]), "+f"(c[2]), "+f"(c[3])
                 : "r"(a[0]), "r"(a[1]), "r"(a[2]), "r"(a[3]), "r"(b[0]), "r"(b[1]));
}
__device__ __forceinline__ unsigned pack_h2(float a, float b) {
    __half2 t = __floats2half2_rn(a, b);
    return *(unsigned*)&t;
}

// ---------------- segment descriptors for fused GEMM launches ----------------
struct Seg {
    const float* W;
    const float* bias;
    float* C;
    int N;
    int tile0;
};
struct Segs {
    Seg s[3];
    int nseg;
};

// ---------------- fused fp16-A x fp32-W tensor-core GEMM ----------------
// MT x 128 x 32 tiles (MT=128: 2x4 warps, 2 CTA/SM; MT=256: 4x2 warps, 1 CTA/SM),
// 3-stage cp.async, in-kernel fp32->fp16 weight conversion.
// MODE 0: dense (M = T_). MODE 1: gather A rows via list. MODE 2: A linear in
// expert buf, scatter C rows.
#define GST 40

template<int MODE, int MT>
__global__ __launch_bounds__(256, (MT == 128) ? 2 : 1)
void gemm_tc(const f16* __restrict__ Ain, Segs segs, int K,
             const float* __restrict__ Res,
             const int* __restrict__ cnt, const int* __restrict__ list) {
    constexpr int A_SB = MT * 80;               // MT rows * 80B fp16 (padded)
    constexpr int STAGE_B = A_SB + 18432;       // + 128 rows * 144B fp32 raw W
    constexpr int WCV_OFF = 3 * STAGE_B;
    constexpr int MW = (MT == 128) ? 2 : 4;     // warps along M
    constexpr int NWN = 8 / MW;                 // warps along N
    constexpr int NI = 128 / (NWN * 8);         // 8-col frags per warp
    constexpr int WN_COLS = NI * 8;

    extern __shared__ __align__(16) char dynsm[];
    __shared__ int s_tok[MT];
    int e = (MODE == 0) ? 0 : blockIdx.z;
    int rows = (MODE == 0) ? T_ : cnt[e];
    int m0 = blockIdx.y * MT;
    if (MODE != 0 && m0 >= rows) return;
    int nt = blockIdx.x;
    Seg sel = segs.s[0];
    if (segs.nseg > 1 && nt >= segs.s[1].tile0) sel = segs.s[1];
    if (segs.nseg > 2 && nt >= segs.s[2].tile0) sel = segs.s[2];
    int n0 = (nt - sel.tile0) * 128;
    int N = sel.N;
    int tid = threadIdx.x;

    const float* B = sel.W + (MODE ? (size_t)e * N * K : 0);
    const f16*  Ah = Ain   + (MODE == 2 ? (size_t)e * CAP * K : 0);

    if (MODE != 0) {
#pragma unroll
        for (int p = 0; p < MT / 256 + 1; p++) {
            int idx = tid + p * 256;
            if (idx < MT) {
                int pos = m0 + idx;
                s_tok[idx] = (pos < rows) ? list[e * CAP + pos] : -1;
            }
        }
        __syncthreads();
    }

    f16* sWf16 = (f16*)(dynsm + WCV_OFF);
    int nk = K / 32;
    auto load_stage = [&](int kt) {
        char* sb = dynsm + (kt % 3) * STAGE_B;
        f16*   sA   = (f16*)sb;
        float* sraw = (float*)(sb + A_SB);
        int k0 = kt * 32;
        // A: MT rows x 32 halves = MT*4 x 16B chunks
#pragma unroll
        for (int p = 0; p < MT / 64; p++) {
            int idx = tid + p * 256;
            int r = idx >> 2, c8 = (idx & 3) << 3;
            unsigned da = sm_u32(sA + r * GST + c8);
            if (MODE == 1) {
                int en = s_tok[r];
                bool pa = en >= 0;
                size_t ro = pa ? (size_t)(en >> 1) * K : 0;
                cp16z(da, Ain + ro + k0 + c8, pa);
            } else {
                cp16(da, Ah + (size_t)(m0 + r) * K + k0 + c8);
            }
        }
        // W fp32: 128 rows x 32 floats = 1024 x 16B chunks
#pragma unroll
        for (int p = 0; p < 4; p++) {
            int idx = tid + p * 256;
            int r = idx >> 3, c4 = (idx & 7) << 2;
            cp16(sm_u32(sraw + r * 36 + c4), B + (size_t)(n0 + r) * K + k0 + c4);
        }
        cp_commit();
    };
    auto conv_stage = [&](int kt) {
        const float* raw = (const float*)(dynsm + (kt % 3) * STAGE_B + A_SB);
        int r = tid >> 1, hf = tid & 1;
        const float* src = raw + r * 36 + hf * 16;
        float4 f0 = *(const float4*)(src + 0);
        float4 f1 = *(const float4*)(src + 4);
        float4 f2 = *(const float4*)(src + 8);
        float4 f3 = *(const float4*)(src + 12);
        __half2 hh[8];
        hh[0] = __floats2half2_rn(f0.x, f0.y); hh[1] = __floats2half2_rn(f0.z, f0.w);
        hh[2] = __floats2half2_rn(f1.x, f1.y); hh[3] = __floats2half2_rn(f1.z, f1.w);
        hh[4] = __floats2half2_rn(f2.x, f2.y); hh[5] = __floats2half2_rn(f2.z, f2.w);
        hh[6] = __floats2half2_rn(f3.x, f3.y); hh[7] = __floats2half2_rn(f3.z, f3.w);
        f16* dst = sWf16 + r * GST + hf * 16;
        *(uint4*)dst = *(uint4*)&hh[0];
        *(uint4*)(dst + 8) = *(uint4*)&hh[4];
    };

    int lane = tid & 31, warp = tid >> 5;
    int wm = warp & (MW - 1), wn = warp / MW;
    unsigned offA = (lane & 15) * (GST * 2) + (lane >> 4) * 16;
    int l4 = lane & 15;
    unsigned offB = (l4 & 7) * (GST * 2) + ((l4 >> 3) & 1) * 16;

    float acc[4][NI][4] = {};

    int npre = (nk < 3) ? nk : 3;
    for (int s = 0; s < npre; s++) load_stage(s);

    for (int kt = 0; kt < nk; kt++) {
        int rem = nk - 1 - kt;
        if (rem >= 2) cp_wait<2>(); else if (rem == 1) cp_wait<1>(); else cp_wait<0>();
        __syncthreads();
        conv_stage(kt);
        __syncthreads();
        char* sb = dynsm + (kt % 3) * STAGE_B;
        unsigned baseA = sm_u32(sb);
        unsigned baseB = sm_u32(sWf16);
#pragma unroll
        for (int ks = 0; ks < 2; ks++) {
            unsigned ah[4][4];
#pragma unroll
            for (int im = 0; im < 4; im++) {
                unsigned off = offA + (unsigned)((wm * 64 + im * 16) * (GST * 2) + ks * 32);
                ldsm4(ah[im][0], ah[im][1], ah[im][2], ah[im][3], baseA + off);
            }
#pragma unroll
            for (int in_ = 0; in_ < NI; in_++) {
                unsigned off = offB + (unsigned)((wn * WN_COLS + in_ * 8) * (GST * 2) + ks * 32);
                unsigned bh[2];
                ldsm2(bh[0], bh[1], baseB + off);
#pragma unroll
                for (int im = 0; im < 4; im++) mma_f16(acc[im][in_], ah[im], bh);
            }
        }
        __syncthreads();
        if (kt + 3 < nk) load_stage(kt + 3);
    }

    // ---- epilogue ----
#pragma unroll
    for (int im = 0; im < 4; im++) {
#pragma unroll
        for (int h2 = 0; h2 < 2; h2++) {
            int r = wm * 64 + im * 16 + (lane >> 2) + h2 * 8;
            int pos = m0 + r;
            size_t crow;
            if (MODE == 0) {
                crow = (size_t)pos;
            } else if (MODE == 1) {
                if (pos >= rows) continue;
                crow = (size_t)(e * CAP + pos);
            } else {
                if (pos >= rows) continue;
                int en = s_tok[r];
                crow = (size_t)((en & 1) * T_ + (en >> 1));
            }
#pragma unroll
            for (int in_ = 0; in_ < NI; in_++) {
                int cc = n0 + wn * WN_COLS + in_ * 8 + (lane & 3) * 2;
                float v0 = acc[im][in_][h2 * 2 + 0];
                float v1 = acc[im][in_][h2 * 2 + 1];
                if (sel.bias) { v0 += sel.bias[cc]; v1 += sel.bias[cc + 1]; }
                if (MODE == 0 && Res) {
                    v0 += Res[(size_t)pos * N + cc];
                    v1 += Res[(size_t)pos * N + cc + 1];
                }
                sel.C[crow * N + cc]     = v0;
                sel.C[crow * N + cc + 1] = v1;
            }
        }
    }
}

// ---------------- RMSNorm + fp16 out ----------------
__global__ void rmsnorm_h_k(const float* __restrict__ x, const float* __restrict__ w,
                            float* __restrict__ yf, f16* __restrict__ hi) {
    int row = blockIdx.x;
    const float* xr = x + (size_t)row * D_;
    float s = 0.f;
    for (int i = threadIdx.x; i < D_; i += 256) { float v = xr[i]; s += v * v; }
    __shared__ float red[256];
    red[threadIdx.x] = s; __syncthreads();
    for (int st = 128; st > 0; st >>= 1) {
        if (threadIdx.x < st) red[threadIdx.x] += red[threadIdx.x + st];
        __syncthreads();
    }
    float inv = rsqrtf(red[0] / (float)D_ + 1e-6f);
    for (int i = threadIdx.x; i < D_; i += 256) {
        float v = w[i] * xr[i] * inv;
        size_t idx = (size_t)row * D_ + i;
        if (yf) yf[idx] = v;
        hi[idx] = __float2half_rn(v);
    }
}

// ---------------- RoPE + fp16 convert ----------------
__global__ void rope_conv_k(const float* __restrict__ q, const float* __restrict__ k,
                            const float* __restrict__ v, const int* __restrict__ pos_ids,
                            f16* __restrict__ qh, f16* __restrict__ kh,
                            f16* __restrict__ vh) {
    int s = blockIdx.x, hh = blockIdx.y, d = threadIdx.x;
    if (hh >= H_ + KVH_) {
        int kv = hh - H_ - KVH_;
        size_t i = ((size_t)s * KVH_ + kv) * HD_ + d;
        vh[i] = __float2half_rn(v[i]);
        return;
    }
    float pos = (float)pos_ids[s];
    int fi = d & 63;
    float ang = pos * exp2f(-0.31143075889f * (float)fi);
    float c = cosf(ang), sn = sinf(ang);
    const float* base; f16* dst;
    if (hh < H_) { size_t i = ((size_t)s * H_ + hh) * HD_; base = q + i; dst = qh + i; }
    else { size_t i = ((size_t)s * KVH_ + (hh - H_)) * HD_; base = k + i; dst = kh + i; }
    float vv = base[d];
    float vr = (d < 64) ? -base[d + 64] : base[d - 64];
    dst[d] = __float2half_rn(vv * c + vr * sn);
}

// ---------------- tensor-core flash attention ----------------
#define ATT_SMEM 104448
__global__ __launch_bounds__(256, 1)
void attn_mma_k(const f16* __restrict__ qh, const f16* __restrict__ kh,
                const f16* __restrict__ vh, f16* __restrict__ ohi) {
    extern __shared__ __align__(16) char sm[];
    f16* Qs = (f16*)sm;
    f16* Ksb[2] = {(f16*)(sm + 34816), (f16*)(sm + 52224)};
    f16* Vsb[2] = {(f16*)(sm + 69632), (f16*)(sm + 87040)};
    int qb = blockIdx.x, h = blockIdx.y, kvh = h >> 2;
    int tid = threadIdx.x, lane = tid & 31, warp = tid >> 5;

#pragma unroll
    for (int i = 0; i < 8; i++) {
        int chunk = tid + i * 256;
        int r = chunk >> 4, c = chunk & 15;
        cp16(sm_u32(Qs + r * 136 + c * 8),
             qh + (((size_t)(qb * 128 + r)) * H_ + h) * HD_ + c * 8);
    }
    cp_commit();
    int nkt = 2 * qb + 2;
    auto load_kv = [&](int kt) {
        int b = kt & 1;
#pragma unroll
        for (int i = 0; i < 4; i++) {
            int chunk = tid + i * 256;
            int r = chunk >> 4, c = chunk & 15;
            size_t gi = (((size_t)(kt * 64 + r)) * KVH_ + kvh) * HD_ + c * 8;
            cp16(sm_u32(Ksb[b] + r * 136 + c * 8), kh + gi);
            cp16(sm_u32(Vsb[b] + r * 136 + c * 8), vh + gi);
        }
        cp_commit();
    };
    load_kv(0);
    cp_wait<1>();
    __syncthreads();

    unsigned qf[8][4];
    {
        unsigned qbase = sm_u32(Qs + warp * 16 * 136);
        unsigned offA = (lane & 15) * 272 + (lane >> 4) * 16;
#pragma unroll
        for (int kc = 0; kc < 8; kc++)
            ldsm4(qf[kc][0], qf[kc][1], qf[kc][2], qf[kc][3], qbase + offA + kc * 32);
    }

    float oacc[16][4] = {};
    float mrow0 = -1e30f, mrow1 = -1e30f, lrow0 = 0.f, lrow1 = 0.f;
    const float scale = 0.08838834764831845f;
    int r0g = qb * 128 + warp * 16 + (lane >> 2);

    for (int kt = 0; kt < nkt; kt++) {
        if (kt + 1 < nkt) { load_kv(kt + 1); cp_wait<1>(); }
        else             { cp_wait<0>(); }
        __syncthreads();
        int b = kt & 1;
        unsigned kbase = sm_u32(Ksb[b]);
        unsigned vbase = sm_u32(Vsb[b]);
        float sacc[8][4] = {};
#pragma unroll
        for (int kc = 0; kc < 8; kc++) {
            unsigned kb[8][2];
#pragma unroll
            for (int np = 0; np < 4; np++) {
                unsigned r0, r1, r2, r3;
                ldsm4(r0, r1, r2, r3,
                      kbase + (unsigned)((np * 16 + (lane & 15)) * 272 + kc * 32 + (lane >> 4) * 16));
                kb[2*np][0] = r0; kb[2*np][1] = r2;
                kb[2*np+1][0] = r1; kb[2*np+1][1] = r3;
            }
#pragma unroll
            for (int n = 0; n < 8; n++) mma_f16(sacc[n], qf[kc], kb[n]);
        }
        bool domask = (kt >= 2 * qb);
#pragma unroll
        for (int n = 0; n < 8; n++) {
            int col = kt * 64 + n * 8 + (lane & 3) * 2;
#pragma unroll
            for (int j = 0; j < 4; j++) {
                float sv = sacc[n][j] * scale;
                if (domask && (col + (j & 1)) > (r0g + (j >> 1) * 8)) sv = -1e30f;
                sacc[n][j] = sv;
            }
        }
        float mx0 = -1e30f, mx1 = -1e30f;
#pragma unroll
        for (int n = 0; n < 8; n++) {
            mx0 = fmaxf(mx0, fmaxf(sacc[n][0], sacc[n][1]));
            mx1 = fmaxf(mx1, fmaxf(sacc[n][2], sacc[n][3]));
        }
        mx0 = fmaxf(mx0, __shfl_xor_sync(0xffffffffu, mx0, 1));
        mx0 = fmaxf(mx0, __shfl_xor_sync(0xffffffffu, mx0, 2));
        mx1 = fmaxf(mx1, __shfl_xor_sync(0xffffffffu, mx1, 1));
        mx1 = fmaxf(mx1, __shfl_xor_sync(0xffffffffu, mx1, 2));
        float mn0 = fmaxf(mrow0, mx0), mn1 = fmaxf(mrow1, mx1);
        float al0 = __expf(mrow0 - mn0), al1 = __expf(mrow1 - mn1);
        mrow0 = mn0; mrow1 = mn1;
        float ps0 = 0.f, ps1 = 0.f;
#pragma unroll
        for (int n = 0; n < 8; n++) {
            sacc[n][0] = __expf(sacc[n][0] - mn0);
            sacc[n][1] = __expf(sacc[n][1] - mn0);
            sacc[n][2] = __expf(sacc[n][2] - mn1);
            sacc[n][3] = __expf(sacc[n][3] - mn1);
            ps0 += sacc[n][0] + sacc[n][1];
            ps1 += sacc[n][2] + sacc[n][3];
        }
        ps0 += __shfl_xor_sync(0xffffffffu, ps0, 1);
        ps0 += __shfl_xor_sync(0xffffffffu, ps0, 2);
        ps1 += __shfl_xor_sync(0xffffffffu, ps1, 1);
        ps1 += __shfl_xor_sync(0xffffffffu, ps1, 2);
        lrow0 = lrow0 * al0 + ps0;
        lrow1 = lrow1 * al1 + ps1;
#pragma unroll
        for (int n = 0; n < 16; n++) {
            oacc[n][0] *= al0; oacc[n][1] *= al0;
            oacc[n][2] *= al1; oacc[n][3] *= al1;
        }
        unsigned pf[4][4];
#pragma unroll
        for (int kc2 = 0; kc2 < 4; kc2++) {
            pf[kc2][0] = pack_h2(sacc[2*kc2][0],   sacc[2*kc2][1]);
            pf[kc2][1] = pack_h2(sacc[2*kc2][2],   sacc[2*kc2][3]);
            pf[kc2][2] = pack_h2(sacc[2*kc2+1][0], sacc[2*kc2+1][1]);
            pf[kc2][3] = pack_h2(sacc[2*kc2+1][2], sacc[2*kc2+1][3]);
        }
#pragma unroll
        for (int kc2 = 0; kc2 < 4; kc2++) {
#pragma unroll
            for (int nd = 0; nd < 8; nd++) {
                unsigned r0, r1, r2, r3;
                ldsm4t(r0, r1, r2, r3,
                       vbase + (unsigned)((kc2 * 16 + (lane & 15)) * 272 + nd * 32 + (lane >> 4) * 16));
                unsigned b0[2] = {r0, r1}, b1[2] = {r2, r3};
                mma_f16(oacc[2*nd],     pf[kc2], b0);
                mma_f16(oacc[2*nd + 1], pf[kc2], b1);
            }
        }
        __syncthreads();
    }
    float inv0 = 1.f / lrow0, inv1 = 1.f / lrow1;
    size_t ob0 = (size_t)r0g * D_ + (size_t)h * HD_;
    size_t ob1 = (size_t)(r0g + 8) * D_ + (size_t)h * HD_;
#pragma unroll
    for (int n = 0; n < 16; n++) {
        int col = n * 8 + (lane & 3) * 2;
        *(__half2*)(ohi + ob0 + col) =
            __floats2half2_rn(oacc[n][0] * inv0, oacc[n][1] * inv0);
        *(__half2*)(ohi + ob1 + col) =
            __floats2half2_rn(oacc[n][2] * inv1, oacc[n][3] * inv1);
    }
}

// ---------------- router ----------------
__global__ void zero_cnt_k(int* cnt) { if (threadIdx.x < E_) cnt[threadIdx.x] = 0; }

__global__ void router_k(const float* __restrict__ x2, const float* __restrict__ rw,
                         float* __restrict__ wslot, int* __restrict__ cnt,
                         int* __restrict__ list) {
    int tok = blockIdx.x;
    int tid = threadIdx.x;
    int w = tid >> 5, lane = tid & 31;
    const float* xr = x2 + (size_t)tok * D_;
    const float* wr = rw + (size_t)w * D_;
    float s = 0.f;
    for (int i = lane; i < D_; i += 32) s += xr[i] * wr[i];
#pragma unroll
    for (int o = 16; o > 0; o >>= 1) s += __shfl_down_sync(0xffffffffu, s, o);
    __shared__ float lg[E_];
    if (lane == 0) lg[w] = s;
    __syncthreads();
    if (tid == 0) {
        float mx = lg[0];
        for (int e = 1; e < E_; e++) mx = fmaxf(mx, lg[e]);
        float p[E_]; float sum = 0.f;
        for (int e = 0; e < E_; e++) { p[e] = expf(lg[e] - mx); sum += p[e]; }
        for (int e = 0; e < E_; e++) p[e] /= sum;
        int i0 = 0;
        for (int e = 1; e < E_; e++) if (p[e] > p[i0]) i0 = e;
        int i1 = (i0 == 0) ? 1 : 0;
        for (int e = 0; e < E_; e++) if (e != i0 && p[e] > p[i1]) i1 = e;
        wslot[tok * 2 + 0] = p[i0];
        wslot[tok * 2 + 1] = p[i1];
        int pos0 = atomicAdd(&cnt[i0], 1); list[i0 * CAP + pos0] = tok * 2 + 0;
        int pos1 = atomicAdd(&cnt[i1], 1); list[i1 * CAP + pos1] = tok * 2 + 1;
    }
}

// ---------------- activations ----------------
__global__ void expert_act_k(const float* __restrict__ g, const float* __restrict__ u,
                             const int* __restrict__ cnt, f16* __restrict__ hi) {
    int e = blockIdx.y, pos = blockIdx.x;
    if (pos >= cnt[e]) return;
    size_t row = (size_t)(e * CAP + pos) * I_;
    for (int i = threadIdx.x; i < I_; i += 256) {
        float gv = g[row + i], uv = u[row + i];
        hi[row + i] = __float2half_rn(gv / (1.f + expf(-gv)) * uv);
    }
}

__global__ void shared_act_k(const float* __restrict__ g, const float* __restrict__ u,
                             f16* __restrict__ hi) {
    size_t row = (size_t)blockIdx.x * SI_;
    for (int i = threadIdx.x; i < SI_; i += 256) {
        float gv = g[row + i], uv = u[row + i];
        hi[row + i] = __float2half_rn(gv / (1.f + expf(-gv)) * uv);
    }
}

__global__ void sgate_k(const float* __restrict__ x2, const float* __restrict__ segw,
                        float* __restrict__ sg) {
    int tok = blockIdx.x; int tid = threadIdx.x;
    const float* xr = x2 + (size_t)tok * D_;
    float s = 0.f;
    for (int i = tid; i < D_; i += 256) s += xr[i] * segw[i];
    __shared__ float red[256];
    red[tid] = s; __syncthreads();
    for (int st = 128; st > 0; st >>= 1) {
        if (tid < st) red[tid] += red[tid + st];
        __syncthreads();
    }
    if (tid == 0) sg[tok] = 1.f / (1.f + expf(-red[0]));
}

__global__ void combine_k(const float* __restrict__ h, const float* __restrict__ moe,
                          const float* __restrict__ wslot, const float* __restrict__ sg,
                          const float* __restrict__ shd, float* __restrict__ out) {
    int tok = blockIdx.x; int tid = threadIdx.x;
    float w0 = wslot[tok * 2], w1 = wslot[tok * 2 + 1], gg = sg[tok];
    for (int d = tid; d < D_; d += 256) {
        size_t i = (size_t)tok * D_ + d;
        out[i] = h[i] + w0 * moe[i] + w1 * moe[(size_t)T_ * D_ + i] + gg * shd[i];
    }
}

// ---------------- launch ----------------
#define SYM(p, s) cudaGetSymbolAddress((void**)&p, s)
#define SMEM128 (3 * (128 * 80 + 18432) + 10240)
#define SMEM256 (3 * (256 * 80 + 18432) + 10240)

extern "C" void kernel_launch(void* const* d_in, const int* in_sizes, int n_in,
                              void* d_out, int out_size) {
    const float* hidden   = (const float*)d_in[0];
    const int*   pos_ids  = (const int*)d_in[1];
    const float* q_w      = (const float*)d_in[2];
    const float* q_b      = (const float*)d_in[3];
    const float* k_w      = (const float*)d_in[4];
    const float* k_b      = (const float*)d_in[5];
    const float* v_w      = (const float*)d_in[6];
    const float* v_b      = (const float*)d_in[7];
    const float* o_w      = (const float*)d_in[8];
    const float* ln1      = (const float*)d_in[9];
    const float* ln2      = (const float*)d_in[10];
    const float* router_w = (const float*)d_in[11];
    const float* eg       = (const float*)d_in[12];
    const float* eu       = (const float*)d_in[13];
    const float* ed       = (const float*)d_in[14];
    const float* sgw      = (const float*)d_in[15];
    const float* suw      = (const float*)d_in[16];
    const float* sdw      = (const float*)d_in[17];
    const float* segw     = (const float*)d_in[18];
    float* out = (float*)d_out;

    float *q, *k, *v, *h, *x2f, *g, *u, *moe, *shg, *shu, *shd, *wslot, *sgate;
    int *cnt, *list;
    SYM(q, d_q); SYM(k, d_k); SYM(v, d_v); SYM(h, d_h); SYM(x2f, d_x2f);
    SYM(g, d_g); SYM(u, d_u); SYM(moe, d_moe);
    SYM(shg, d_shg); SYM(shu, d_shu); SYM(shd, d_shd);
    SYM(wslot, d_wslot); SYM(sgate, d_sgate); SYM(cnt, d_cnt); SYM(list, d_list);
    f16 *qh, *kh, *vh, *xnh, *x2h, *aoh, *gah, *sah;
    SYM(qh, d_qh); SYM(kh, d_kh); SYM(vh, d_vh);
    SYM(xnh, d_xn_h); SYM(x2h, d_x2_h); SYM(aoh, d_ao_h);
    SYM(gah, d_ga_h); SYM(sah, d_sa_h);

    cudaFuncSetAttribute(gemm_tc<0, 128>, cudaFuncAttributeMaxDynamicSharedMemorySize, SMEM128);
    cudaFuncSetAttribute(gemm_tc<2, 128>, cudaFuncAttributeMaxDynamicSharedMemorySize, SMEM128);
    cudaFuncSetAttribute(gemm_tc<0, 256>, cudaFuncAttributeMaxDynamicSharedMemorySize, SMEM256);
    cudaFuncSetAttribute(gemm_tc<1, 256>, cudaFuncAttributeMaxDynamicSharedMemorySize, SMEM256);
    cudaFuncSetAttribute(gemm_tc<2, 256>, cudaFuncAttributeMaxDynamicSharedMemorySize, SMEM256);
    cudaFuncSetAttribute(attn_mma_k, cudaFuncAttributeMaxDynamicSharedMemorySize, ATT_SMEM);

    Seg z = {nullptr, nullptr, nullptr, 0, 0};

    Segs qkv = {{{q_w, q_b, q, D_, 0},
                 {k_w, k_b, k, KVH_ * HD_, 16},
                 {v_w, v_b, v, KVH_ * HD_, 20}}, 3};
    Segs oseg = {{{o_w, nullptr, h, D_, 0}, z, z}, 1};
    Segs egu  = {{{eg, nullptr, g, I_, 0},
                  {eu, nullptr, u, I_, 11}, z}, 2};
    Segs edn  = {{{ed, nullptr, moe, D_, 0}, z, z}, 1};
    Segs sgu  = {{{sgw, nullptr, shg, SI_, 0},
                  {suw, nullptr, shu, SI_, 44}, z}, 2};
    Segs sdn  = {{{sdw, nullptr, shd, D_, 0}, z, z}, 1};

    // ---- attention path ----
    rmsnorm_h_k<<<T_, 256>>>(hidden, ln1, nullptr, xnh);
    gemm_tc<0, 128><<<dim3(24, 8), 256, SMEM128>>>(xnh, qkv, D_, nullptr, nullptr, nullptr);
    rope_conv_k<<<dim3(T_, H_ + 2 * KVH_), HD_>>>(q, k, v, pos_ids, qh, kh, vh);
    attn_mma_k<<<dim3(8, H_), 256, ATT_SMEM>>>(qh, kh, vh, aoh);
    gemm_tc<0, 128><<<dim3(16, 8), 256, SMEM128>>>(aoh, oseg, D_, hidden, nullptr, nullptr);

    // ---- MoE path ----
    rmsnorm_h_k<<<T_, 256>>>(h, ln2, x2f, x2h);
    zero_cnt_k<<<1, 32>>>(cnt);
    router_k<<<T_, 256>>>(x2f, router_w, wslot, cnt, list);
    gemm_tc<1, 256><<<dim3(22, 4, E_), 256, SMEM256>>>(x2h, egu, D_, nullptr, cnt, list);
    expert_act_k<<<dim3(CAP, E_), 256>>>(g, u, cnt, gah);
    gemm_tc<2, 256><<<dim3(16, 4, E_), 256, SMEM256>>>(gah, edn, I_, nullptr, cnt, list);
    gemm_tc<0, 256><<<dim3(88, 4), 256, SMEM256>>>(x2h, sgu, D_, nullptr, nullptr, nullptr);
    shared_act_k<<<T_, 256>>>(shg, shu, sah);
    gemm_tc<0, 128><<<dim3(16, 8), 256, SMEM128>>>(sah, sdn, SI_, nullptr, nullptr, nullptr);
    sgate_k<<<T_, 256>>>(x2f, segw, sgate);
    combine_k<<<T_, 256>>>(h, moe, wslot, sgate, shd, out);
}

// round 14
// speedup vs baseline: 1.2473x; 1.2473x over previous
#include <cuda_runtime.h>
#include <cuda_fp16.h>
#include <math.h>
#include <stdint.h>

#define D_    2048
#define H_    16
#define KVH_  4
#define HD_   128
#define E_    8
#define I_    1408
#define SI_   5632
#define T_    1024
#define CAP   1024

typedef __half f16;

// ---------------- scratch (device globals; allocation-free) ----------------
__device__ float d_q[T_ * D_];
__device__ float d_k[T_ * KVH_ * HD_];
__device__ float d_v[T_ * KVH_ * HD_];
__device__ float d_h[T_ * D_];
__device__ float d_x2f[T_ * D_];
__device__ float d_g[E_ * CAP * I_];
__device__ float d_u[E_ * CAP * I_];
__device__ float d_moe[2 * T_ * D_];
__device__ float d_shg[T_ * SI_];
__device__ float d_shu[T_ * SI_];
__device__ float d_shd[T_ * D_];
__device__ float d_wslot[T_ * 2];
__device__ float d_sgate[T_];
__device__ int   d_cnt[E_];
__device__ int   d_list[E_ * CAP];
__device__ f16 d_qh[T_ * D_];
__device__ f16 d_kh[T_ * KVH_ * HD_];
__device__ f16 d_vh[T_ * KVH_ * HD_];
__device__ f16 d_xn_h[T_ * D_];
__device__ f16 d_x2_h[T_ * D_];
__device__ f16 d_ao_h[T_ * D_];
__device__ f16 d_ga_h[E_ * CAP * I_];
__device__ f16 d_sa_h[T_ * SI_];
// fp16 weights (converted once per launch)
__device__ f16 w_q16[D_ * D_];
__device__ f16 w_k16[KVH_*HD_ * D_];
__device__ f16 w_v16[KVH_*HD_ * D_];
__device__ f16 w_o16[D_ * D_];
__device__ f16 w_eg16[E_ * I_ * D_];
__device__ f16 w_eu16[E_ * I_ * D_];
__device__ f16 w_ed16[E_ * D_ * I_];
__device__ f16 w_sg16[SI_ * D_];
__device__ f16 w_su16[SI_ * D_];
__device__ f16 w_sd16[D_ * SI_];

// ---------------- PTX helpers ----------------
__device__ __forceinline__ unsigned sm_u32(const void* p) {
    return (unsigned)__cvta_generic_to_shared(p);
}
__device__ __forceinline__ void cp16(unsigned dst, const void* src) {
    asm volatile("cp.async.cg.shared.global [%0], [%1], 16;\n" :: "r"(dst), "l"(src));
}
__device__ __forceinline__ void cp16z(unsigned dst, const void* src, bool pred) {
    int sz = pred ? 16 : 0;
    asm volatile("cp.async.cg.shared.global [%0], [%1], 16, %2;\n" :: "r"(dst), "l"(src), "r"(sz));
}
__device__ __forceinline__ void cp_commit() { asm volatile("cp.async.commit_group;\n"); }
template<int N> __device__ __forceinline__ void cp_wait() {
    asm volatile("cp.async.wait_group %0;\n" :: "n"(N));
}
__device__ __forceinline__ void ldsm4(unsigned& r0, unsigned& r1, unsigned& r2, unsigned& r3, unsigned a) {
    asm volatile("ldmatrix.sync.aligned.m8n8.x4.shared.b16 {%0,%1,%2,%3}, [%4];\n"
                 : "=r"(r0), "=r"(r1), "=r"(r2), "=r"(r3) : "r"(a));
}
__device__ __forceinline__ void ldsm4t(unsigned& r0, unsigned& r1, unsigned& r2, unsigned& r3, unsigned a) {
    asm volatile("ldmatrix.sync.aligned.m8n8.x4.trans.shared.b16 {%0,%1,%2,%3}, [%4];\n"
                 : "=r"(r0), "=r"(r1), "=r"(r2), "=r"(r3) : "r"(a));
}
__device__ __forceinline__ void ldsm2(unsigned& r0, unsigned& r1, unsigned a) {
    asm volatile("ldmatrix.sync.aligned.m8n8.x2.shared.b16 {%0,%1}, [%2];\n"
                 : "=r"(r0), "=r"(r1) : "r"(a));
}
__device__ __forceinline__ void mma_f16(float* c, const unsigned* a, const unsigned* b) {
    asm volatile("mma.sync.aligned.m16n8k16.row.col.f32.f16.f16.f32 "
                 "{%0,%1,%2,%3}, {%4,%5,%6,%7}, {%8,%9}, {%0,%1,%2,%3};\n"
                 : "+f"(c[0]), "+f"(c[1]), "+f"(c[2]), "+f"(c[3])
                 : "r"(a[0]), "r"(a[1]), "r"(a[2]), "r"(a[3]), "r"(b[0]), "r"(b[1]));
}
__device__ __forceinline__ unsigned pack_h2(float a, float b) {
    __half2 t = __floats2half2_rn(a, b);
    return *(unsigned*)&t;
}

// ---------------- weight convert fp32 -> fp16 (16 elems/thread, MLP=4) ----------------
__global__ void wconv16_k(const float* __restrict__ x, f16* __restrict__ hi, int n16) {
    int i = blockIdx.x * 256 + threadIdx.x;
    if (i >= n16) return;
    const float4* src = (const float4*)x + 4 * (size_t)i;
    float4 a = src[0], b = src[1], c = src[2], d = src[3];
    __half2 hp[8];
    hp[0] = __floats2half2_rn(a.x, a.y); hp[1] = __floats2half2_rn(a.z, a.w);
    hp[2] = __floats2half2_rn(b.x, b.y); hp[3] = __floats2half2_rn(b.z, b.w);
    hp[4] = __floats2half2_rn(c.x, c.y); hp[5] = __floats2half2_rn(c.z, c.w);
    hp[6] = __floats2half2_rn(d.x, d.y); hp[7] = __floats2half2_rn(d.z, d.w);
    uint4* dst = (uint4*)hi + 2 * (size_t)i;
    dst[0] = *(uint4*)&hp[0];
    dst[1] = *(uint4*)&hp[4];
}

// ---------------- segment descriptors for fused GEMM launches ----------------
struct Seg {
    const f16* W;
    const float* bias;
    float* C;
    int N;
    int tile0;
};
struct Segs {
    Seg s[3];
    int nseg;
};

// ---------------- fp16 x fp16 tensor-core GEMM ----------------
// 128x128x32 tiles, 256 threads (2x4 warps, 64x32 warp tile), 3-stage cp.async,
// 2 CTAs/SM. MODE 0: dense (M = T_). MODE 1: gather A rows via list.
// MODE 2: A linear in expert buf, scatter C rows.
#define GST 40
#define TILE_SB 10240                 // 128 rows * 80B fp16 (padded)
#define STAGE_B 20480                 // A + W
#define GEMM_SMEM (3 * STAGE_B)       // 61440

template<int MODE>
__global__ __launch_bounds__(256, 2)
void gemm_tc(const f16* __restrict__ Ain, Segs segs, int K,
             const float* __restrict__ Res,
             const int* __restrict__ cnt, const int* __restrict__ list) {
    extern __shared__ __align__(16) char dynsm[];
    __shared__ int s_tok[128];
    int e = (MODE == 0) ? 0 : blockIdx.z;
    int rows = (MODE == 0) ? T_ : cnt[e];
    int m0 = blockIdx.y * 128;
    if (MODE != 0 && m0 >= rows) return;
    int nt = blockIdx.x;
    Seg sel = segs.s[0];
    if (segs.nseg > 1 && nt >= segs.s[1].tile0) sel = segs.s[1];
    if (segs.nseg > 2 && nt >= segs.s[2].tile0) sel = segs.s[2];
    int n0 = (nt - sel.tile0) * 128;
    int N = sel.N;
    int tid = threadIdx.x;

    const f16* B  = sel.W + (MODE ? (size_t)e * N * K : 0);
    const f16* Ah = Ain   + (MODE == 2 ? (size_t)e * CAP * K : 0);

    if (MODE != 0) {
        if (tid < 128) {
            int pos = m0 + tid;
            s_tok[tid] = (pos < rows) ? list[e * CAP + pos] : -1;
        }
        __syncthreads();
    }

    int nk = K / 32;
    auto load_stage = [&](int kt) {
        char* sb = dynsm + (kt % 3) * STAGE_B;
        f16* sA = (f16*)sb;
        f16* sB = (f16*)(sb + TILE_SB);
        int k0 = kt * 32;
#pragma unroll
        for (int p = 0; p < 2; p++) {
            int idx = tid + p * 256;
            int r = idx >> 2, c8 = (idx & 3) << 3;
            unsigned da = sm_u32(sA + r * GST + c8);
            if (MODE == 1) {
                int en = s_tok[r];
                bool pa = en >= 0;
                size_t ro = pa ? (size_t)(en >> 1) * K : 0;
                cp16z(da, Ain + ro + k0 + c8, pa);
            } else {
                cp16(da, Ah + (size_t)(m0 + r) * K + k0 + c8);
            }
            cp16(sm_u32(sB + r * GST + c8), B + (size_t)(n0 + r) * K + k0 + c8);
        }
        cp_commit();
    };

    int lane = tid & 31, warp = tid >> 5;
    int wm = warp & 1, wn = warp >> 1;
    unsigned offA = (lane & 15) * (GST * 2) + (lane >> 4) * 16;
    int l4 = lane & 15;
    unsigned offB = (l4 & 7) * (GST * 2) + ((l4 >> 3) & 1) * 16;

    float acc[4][4][4] = {};

    int npre = (nk < 3) ? nk : 3;
    for (int s = 0; s < npre; s++) load_stage(s);

    for (int kt = 0; kt < nk; kt++) {
        int rem = nk - 1 - kt;
        if (rem >= 2) cp_wait<2>(); else if (rem == 1) cp_wait<1>(); else cp_wait<0>();
        __syncthreads();
        char* sb = dynsm + (kt % 3) * STAGE_B;
        unsigned baseA = sm_u32(sb);
        unsigned baseB = baseA + TILE_SB;
#pragma unroll
        for (int ks = 0; ks < 2; ks++) {
            unsigned ah[4][4];
#pragma unroll
            for (int im = 0; im < 4; im++) {
                unsigned off = offA + (unsigned)((wm * 64 + im * 16) * (GST * 2) + ks * 32);
                ldsm4(ah[im][0], ah[im][1], ah[im][2], ah[im][3], baseA + off);
            }
#pragma unroll
            for (int in_ = 0; in_ < 4; in_++) {
                unsigned off = offB + (unsigned)((wn * 32 + in_ * 8) * (GST * 2) + ks * 32);
                unsigned bh[2];
                ldsm2(bh[0], bh[1], baseB + off);
#pragma unroll
                for (int im = 0; im < 4; im++) mma_f16(acc[im][in_], ah[im], bh);
            }
        }
        __syncthreads();
        if (kt + 3 < nk) load_stage(kt + 3);
    }

    // ---- epilogue ----
#pragma unroll
    for (int im = 0; im < 4; im++) {
#pragma unroll
        for (int h2 = 0; h2 < 2; h2++) {
            int r = wm * 64 + im * 16 + (lane >> 2) + h2 * 8;
            int pos = m0 + r;
            size_t crow;
            if (MODE == 0) {
                crow = (size_t)pos;
            } else if (MODE == 1) {
                if (pos >= rows) continue;
                crow = (size_t)(e * CAP + pos);
            } else {
                if (pos >= rows) continue;
                int en = s_tok[r];
                crow = (size_t)((en & 1) * T_ + (en >> 1));
            }
#pragma unroll
            for (int in_ = 0; in_ < 4; in_++) {
                int cc = n0 + wn * 32 + in_ * 8 + (lane & 3) * 2;
                float v0 = acc[im][in_][h2 * 2 + 0];
                float v1 = acc[im][in_][h2 * 2 + 1];
                if (sel.bias) { v0 += sel.bias[cc]; v1 += sel.bias[cc + 1]; }
                if (MODE == 0 && Res) {
                    v0 += Res[(size_t)pos * N + cc];
                    v1 += Res[(size_t)pos * N + cc + 1];
                }
                sel.C[crow * N + cc]     = v0;
                sel.C[crow * N + cc + 1] = v1;
            }
        }
    }
}

// ---------------- RMSNorm + fp16 out ----------------
__global__ void rmsnorm_h_k(const float* __restrict__ x, const float* __restrict__ w,
                            float* __restrict__ yf, f16* __restrict__ hi) {
    int row = blockIdx.x;
    const float* xr = x + (size_t)row * D_;
    float s = 0.f;
    for (int i = threadIdx.x; i < D_; i += 256) { float v = xr[i]; s += v * v; }
    __shared__ float red[256];
    red[threadIdx.x] = s; __syncthreads();
    for (int st = 128; st > 0; st >>= 1) {
        if (threadIdx.x < st) red[threadIdx.x] += red[threadIdx.x + st];
        __syncthreads();
    }
    float inv = rsqrtf(red[0] / (float)D_ + 1e-6f);
    for (int i = threadIdx.x; i < D_; i += 256) {
        float v = w[i] * xr[i] * inv;
        size_t idx = (size_t)row * D_ + i;
        if (yf) yf[idx] = v;
        hi[idx] = __float2half_rn(v);
    }
}

// ---------------- RoPE + fp16 convert ----------------
__global__ void rope_conv_k(const float* __restrict__ q, const float* __restrict__ k,
                            const float* __restrict__ v, const int* __restrict__ pos_ids,
                            f16* __restrict__ qh, f16* __restrict__ kh,
                            f16* __restrict__ vh) {
    int s = blockIdx.x, hh = blockIdx.y, d = threadIdx.x;
    if (hh >= H_ + KVH_) {
        int kv = hh - H_ - KVH_;
        size_t i = ((size_t)s * KVH_ + kv) * HD_ + d;
        vh[i] = __float2half_rn(v[i]);
        return;
    }
    float pos = (float)pos_ids[s];
    int fi = d & 63;
    float ang = pos * exp2f(-0.31143075889f * (float)fi);
    float c = cosf(ang), sn = sinf(ang);
    const float* base; f16* dst;
    if (hh < H_) { size_t i = ((size_t)s * H_ + hh) * HD_; base = q + i; dst = qh + i; }
    else { size_t i = ((size_t)s * KVH_ + (hh - H_)) * HD_; base = k + i; dst = kh + i; }
    float vv = base[d];
    float vr = (d < 64) ? -base[d + 64] : base[d - 64];
    dst[d] = __float2half_rn(vv * c + vr * sn);
}

// ---------------- tensor-core flash attention ----------------
#define ATT_SMEM 104448
__global__ __launch_bounds__(256, 1)
void attn_mma_k(const f16* __restrict__ qh, const f16* __restrict__ kh,
                const f16* __restrict__ vh, f16* __restrict__ ohi) {
    extern __shared__ __align__(16) char sm[];
    f16* Qs = (f16*)sm;
    f16* Ksb[2] = {(f16*)(sm + 34816), (f16*)(sm + 52224)};
    f16* Vsb[2] = {(f16*)(sm + 69632), (f16*)(sm + 87040)};
    int qb = blockIdx.x, h = blockIdx.y, kvh = h >> 2;
    int tid = threadIdx.x, lane = tid & 31, warp = tid >> 5;

#pragma unroll
    for (int i = 0; i < 8; i++) {
        int chunk = tid + i * 256;
        int r = chunk >> 4, c = chunk & 15;
        cp16(sm_u32(Qs + r * 136 + c * 8),
             qh + (((size_t)(qb * 128 + r)) * H_ + h) * HD_ + c * 8);
    }
    cp_commit();
    int nkt = 2 * qb + 2;
    auto load_kv = [&](int kt) {
        int b = kt & 1;
#pragma unroll
        for (int i = 0; i < 4; i++) {
            int chunk = tid + i * 256;
            int r = chunk >> 4, c = chunk & 15;
            size_t gi = (((size_t)(kt * 64 + r)) * KVH_ + kvh) * HD_ + c * 8;
            cp16(sm_u32(Ksb[b] + r * 136 + c * 8), kh + gi);
            cp16(sm_u32(Vsb[b] + r * 136 + c * 8), vh + gi);
        }
        cp_commit();
    };
    load_kv(0);
    cp_wait<1>();
    __syncthreads();

    unsigned qf[8][4];
    {
        unsigned qbase = sm_u32(Qs + warp * 16 * 136);
        unsigned offA = (lane & 15) * 272 + (lane >> 4) * 16;
#pragma unroll
        for (int kc = 0; kc < 8; kc++)
            ldsm4(qf[kc][0], qf[kc][1], qf[kc][2], qf[kc][3], qbase + offA + kc * 32);
    }

    float oacc[16][4] = {};
    float mrow0 = -1e30f, mrow1 = -1e30f, lrow0 = 0.f, lrow1 = 0.f;
    const float scale = 0.08838834764831845f;
    int r0g = qb * 128 + warp * 16 + (lane >> 2);

    for (int kt = 0; kt < nkt; kt++) {
        if (kt + 1 < nkt) { load_kv(kt + 1); cp_wait<1>(); }
        else             { cp_wait<0>(); }
        __syncthreads();
        int b = kt & 1;
        unsigned kbase = sm_u32(Ksb[b]);
        unsigned vbase = sm_u32(Vsb[b]);
        float sacc[8][4] = {};
#pragma unroll
        for (int kc = 0; kc < 8; kc++) {
            unsigned kb[8][2];
#pragma unroll
            for (int np = 0; np < 4; np++) {
                unsigned r0, r1, r2, r3;
                ldsm4(r0, r1, r2, r3,
                      kbase + (unsigned)((np * 16 + (lane & 15)) * 272 + kc * 32 + (lane >> 4) * 16));
                kb[2*np][0] = r0; kb[2*np][1] = r2;
                kb[2*np+1][0] = r1; kb[2*np+1][1] = r3;
            }
#pragma unroll
            for (int n = 0; n < 8; n++) mma_f16(sacc[n], qf[kc], kb[n]);
        }
        bool domask = (kt >= 2 * qb);
#pragma unroll
        for (int n = 0; n < 8; n++) {
            int col = kt * 64 + n * 8 + (lane & 3) * 2;
#pragma unroll
            for (int j = 0; j < 4; j++) {
                float sv = sacc[n][j] * scale;
                if (domask && (col + (j & 1)) > (r0g + (j >> 1) * 8)) sv = -1e30f;
                sacc[n][j] = sv;
            }
        }
        float mx0 = -1e30f, mx1 = -1e30f;
#pragma unroll
        for (int n = 0; n < 8; n++) {
            mx0 = fmaxf(mx0, fmaxf(sacc[n][0], sacc[n][1]));
            mx1 = fmaxf(mx1, fmaxf(sacc[n][2], sacc[n][3]));
        }
        mx0 = fmaxf(mx0, __shfl_xor_sync(0xffffffffu, mx0, 1));
        mx0 = fmaxf(mx0, __shfl_xor_sync(0xffffffffu, mx0, 2));
        mx1 = fmaxf(mx1, __shfl_xor_sync(0xffffffffu, mx1, 1));
        mx1 = fmaxf(mx1, __shfl_xor_sync(0xffffffffu, mx1, 2));
        float mn0 = fmaxf(mrow0, mx0), mn1 = fmaxf(mrow1, mx1);
        float al0 = __expf(mrow0 - mn0), al1 = __expf(mrow1 - mn1);
        mrow0 = mn0; mrow1 = mn1;
        float ps0 = 0.f, ps1 = 0.f;
#pragma unroll
        for (int n = 0; n < 8; n++) {
            sacc[n][0] = __expf(sacc[n][0] - mn0);
            sacc[n][1] = __expf(sacc[n][1] - mn0);
            sacc[n][2] = __expf(sacc[n][2] - mn1);
            sacc[n][3] = __expf(sacc[n][3] - mn1);
            ps0 += sacc[n][0] + sacc[n][1];
            ps1 += sacc[n][2] + sacc[n][3];
        }
        ps0 += __shfl_xor_sync(0xffffffffu, ps0, 1);
        ps0 += __shfl_xor_sync(0xffffffffu, ps0, 2);
        ps1 += __shfl_xor_sync(0xffffffffu, ps1, 1);
        ps1 += __shfl_xor_sync(0xffffffffu, ps1, 2);
        lrow0 = lrow0 * al0 + ps0;
        lrow1 = lrow1 * al1 + ps1;
#pragma unroll
        for (int n = 0; n < 16; n++) {
            oacc[n][0] *= al0; oacc[n][1] *= al0;
            oacc[n][2] *= al1; oacc[n][3] *= al1;
        }
        unsigned pf[4][4];
#pragma unroll
        for (int kc2 = 0; kc2 < 4; kc2++) {
            pf[kc2][0] = pack_h2(sacc[2*kc2][0],   sacc[2*kc2][1]);
            pf[kc2][1] = pack_h2(sacc[2*kc2][2],   sacc[2*kc2][3]);
            pf[kc2][2] = pack_h2(sacc[2*kc2+1][0], sacc[2*kc2+1][1]);
            pf[kc2][3] = pack_h2(sacc[2*kc2+1][2], sacc[2*kc2+1][3]);
        }
#pragma unroll
        for (int kc2 = 0; kc2 < 4; kc2++) {
#pragma unroll
            for (int nd = 0; nd < 8; nd++) {
                unsigned r0, r1, r2, r3;
                ldsm4t(r0, r1, r2, r3,
                       vbase + (unsigned)((kc2 * 16 + (lane & 15)) * 272 + nd * 32 + (lane >> 4) * 16));
                unsigned b0[2] = {r0, r1}, b1[2] = {r2, r3};
                mma_f16(oacc[2*nd],     pf[kc2], b0);
                mma_f16(oacc[2*nd + 1], pf[kc2], b1);
            }
        }
        __syncthreads();
    }
    float inv0 = 1.f / lrow0, inv1 = 1.f / lrow1;
    size_t ob0 = (size_t)r0g * D_ + (size_t)h * HD_;
    size_t ob1 = (size_t)(r0g + 8) * D_ + (size_t)h * HD_;
#pragma unroll
    for (int n = 0; n < 16; n++) {
        int col = n * 8 + (lane & 3) * 2;
        *(__half2*)(ohi + ob0 + col) =
            __floats2half2_rn(oacc[n][0] * inv0, oacc[n][1] * inv0);
        *(__half2*)(ohi + ob1 + col) =
            __floats2half2_rn(oacc[n][2] * inv1, oacc[n][3] * inv1);
    }
}

// ---------------- router ----------------
__global__ void zero_cnt_k(int* cnt) { if (threadIdx.x < E_) cnt[threadIdx.x] = 0; }

__global__ void router_k(const float* __restrict__ x2, const float* __restrict__ rw,
                         float* __restrict__ wslot, int* __restrict__ cnt,
                         int* __restrict__ list) {
    int tok = blockIdx.x;
    int tid = threadIdx.x;
    int w = tid >> 5, lane = tid & 31;
    const float* xr = x2 + (size_t)tok * D_;
    const float* wr = rw + (size_t)w * D_;
    float s = 0.f;
    for (int i = lane; i < D_; i += 32) s += xr[i] * wr[i];
#pragma unroll
    for (int o = 16; o > 0; o >>= 1) s += __shfl_down_sync(0xffffffffu, s, o);
    __shared__ float lg[E_];
    if (lane == 0) lg[w] = s;
    __syncthreads();
    if (tid == 0) {
        float mx = lg[0];
        for (int e = 1; e < E_; e++) mx = fmaxf(mx, lg[e]);
        float p[E_]; float sum = 0.f;
        for (int e = 0; e < E_; e++) { p[e] = expf(lg[e] - mx); sum += p[e]; }
        for (int e = 0; e < E_; e++) p[e] /= sum;
        int i0 = 0;
        for (int e = 1; e < E_; e++) if (p[e] > p[i0]) i0 = e;
        int i1 = (i0 == 0) ? 1 : 0;
        for (int e = 0; e < E_; e++) if (e != i0 && p[e] > p[i1]) i1 = e;
        wslot[tok * 2 + 0] = p[i0];
        wslot[tok * 2 + 1] = p[i1];
        int pos0 = atomicAdd(&cnt[i0], 1); list[i0 * CAP + pos0] = tok * 2 + 0;
        int pos1 = atomicAdd(&cnt[i1], 1); list[i1 * CAP + pos1] = tok * 2 + 1;
    }
}

// ---------------- activations ----------------
__global__ void expert_act_k(const float* __restrict__ g, const float* __restrict__ u,
                             const int* __restrict__ cnt, f16* __restrict__ hi) {
    int e = blockIdx.y, pos = blockIdx.x;
    if (pos >= cnt[e]) return;
    size_t row = (size_t)(e * CAP + pos) * I_;
    for (int i = threadIdx.x; i < I_; i += 256) {
        float gv = g[row + i], uv = u[row + i];
        hi[row + i] = __float2half_rn(gv / (1.f + expf(-gv)) * uv);
    }
}

__global__ void shared_act_k(const float* __restrict__ g, const float* __restrict__ u,
                             f16* __restrict__ hi) {
    size_t row = (size_t)blockIdx.x * SI_;
    for (int i = threadIdx.x; i < SI_; i += 256) {
        float gv = g[row + i], uv = u[row + i];
        hi[row + i] = __float2half_rn(gv / (1.f + expf(-gv)) * uv);
    }
}

__global__ void sgate_k(const float* __restrict__ x2, const float* __restrict__ segw,
                        float* __restrict__ sg) {
    int tok = blockIdx.x; int tid = threadIdx.x;
    const float* xr = x2 + (size_t)tok * D_;
    float s = 0.f;
    for (int i = tid; i < D_; i += 256) s += xr[i] * segw[i];
    __shared__ float red[256];
    red[tid] = s; __syncthreads();
    for (int st = 128; st > 0; st >>= 1) {
        if (tid < st) red[tid] += red[tid + st];
        __syncthreads();
    }
    if (tid == 0) sg[tok] = 1.f / (1.f + expf(-red[0]));
}

__global__ void combine_k(const float* __restrict__ h, const float* __restrict__ moe,
                          const float* __restrict__ wslot, const float* __restrict__ sg,
                          const float* __restrict__ shd, float* __restrict__ out) {
    int tok = blockIdx.x; int tid = threadIdx.x;
    float w0 = wslot[tok * 2], w1 = wslot[tok * 2 + 1], gg = sg[tok];
    for (int d = tid; d < D_; d += 256) {
        size_t i = (size_t)tok * D_ + d;
        out[i] = h[i] + w0 * moe[i] + w1 * moe[(size_t)T_ * D_ + i] + gg * shd[i];
    }
}

// ---------------- launch ----------------
#define SYM(p, s) cudaGetSymbolAddress((void**)&p, s)

extern "C" void kernel_launch(void* const* d_in, const int* in_sizes, int n_in,
                              void* d_out, int out_size) {
    const float* hidden   = (const float*)d_in[0];
    const int*   pos_ids  = (const int*)d_in[1];
    const float* q_w      = (const float*)d_in[2];
    const float* q_b      = (const float*)d_in[3];
    const float* k_w      = (const float*)d_in[4];
    const float* k_b      = (const float*)d_in[5];
    const float* v_w      = (const float*)d_in[6];
    const float* v_b      = (const float*)d_in[7];
    const float* o_w      = (const float*)d_in[8];
    const float* ln1      = (const float*)d_in[9];
    const float* ln2      = (const float*)d_in[10];
    const float* router_w = (const float*)d_in[11];
    const float* eg       = (const float*)d_in[12];
    const float* eu       = (const float*)d_in[13];
    const float* ed       = (const float*)d_in[14];
    const float* sgw      = (const float*)d_in[15];
    const float* suw      = (const float*)d_in[16];
    const float* sdw      = (const float*)d_in[17];
    const float* segw     = (const float*)d_in[18];
    float* out = (float*)d_out;

    float *q, *k, *v, *h, *x2f, *g, *u, *moe, *shg, *shu, *shd, *wslot, *sgate;
    int *cnt, *list;
    SYM(q, d_q); SYM(k, d_k); SYM(v, d_v); SYM(h, d_h); SYM(x2f, d_x2f);
    SYM(g, d_g); SYM(u, d_u); SYM(moe, d_moe);
    SYM(shg, d_shg); SYM(shu, d_shu); SYM(shd, d_shd);
    SYM(wslot, d_wslot); SYM(sgate, d_sgate); SYM(cnt, d_cnt); SYM(list, d_list);
    f16 *qh, *kh, *vh, *xnh, *x2h, *aoh, *gah, *sah;
    SYM(qh, d_qh); SYM(kh, d_kh); SYM(vh, d_vh);
    SYM(xnh, d_xn_h); SYM(x2h, d_x2_h); SYM(aoh, d_ao_h);
    SYM(gah, d_ga_h); SYM(sah, d_sa_h);
    f16 *qw, *kw, *vw, *ow, *egw16, *euw16, *edw16, *sgw16, *suw16, *sdw16;
    SYM(qw, w_q16); SYM(kw, w_k16); SYM(vw, w_v16); SYM(ow, w_o16);
    SYM(egw16, w_eg16); SYM(euw16, w_eu16); SYM(edw16, w_ed16);
    SYM(sgw16, w_sg16); SYM(suw16, w_su16); SYM(sdw16, w_sd16);

    cudaFuncSetAttribute(gemm_tc<0>, cudaFuncAttributeMaxDynamicSharedMemorySize, GEMM_SMEM);
    cudaFuncSetAttribute(gemm_tc<1>, cudaFuncAttributeMaxDynamicSharedMemorySize, GEMM_SMEM);
    cudaFuncSetAttribute(gemm_tc<2>, cudaFuncAttributeMaxDynamicSharedMemorySize, GEMM_SMEM);
    cudaFuncSetAttribute(attn_mma_k, cudaFuncAttributeMaxDynamicSharedMemorySize, ATT_SMEM);

    auto wconv = [&](const float* src, f16* dst, int n) {
        wconv16_k<<<(n / 16 + 255) / 256, 256>>>(src, dst, n / 16);
    };

    Seg z = {nullptr, nullptr, nullptr, 0, 0};

    Segs qkv = {{{qw, q_b, q, D_, 0},
                 {kw, k_b, k, KVH_ * HD_, 16},
                 {vw, v_b, v, KVH_ * HD_, 20}}, 3};
    Segs oseg = {{{ow, nullptr, h, D_, 0}, z, z}, 1};
    Segs egu  = {{{egw16, nullptr, g, I_, 0},
                  {euw16, nullptr, u, I_, 11}, z}, 2};
    Segs edn  = {{{edw16, nullptr, moe, D_, 0}, z, z}, 1};
    Segs sgu  = {{{sgw16, nullptr, shg, SI_, 0},
                  {suw16, nullptr, shu, SI_, 44}, z}, 2};
    Segs sdn  = {{{sdw16, nullptr, shd, D_, 0}, z, z}, 1};

    // ---- weight conversions (one streaming pass) ----
    wconv(q_w, qw, D_ * D_);
    wconv(k_w, kw, KVH_ * HD_ * D_);
    wconv(v_w, vw, KVH_ * HD_ * D_);
    wconv(o_w, ow, D_ * D_);
    wconv(eg,  egw16, E_ * I_ * D_);
    wconv(eu,  euw16, E_ * I_ * D_);
    wconv(ed,  edw16, E_ * D_ * I_);
    wconv(sgw, sgw16, SI_ * D_);
    wconv(suw, suw16, SI_ * D_);
    wconv(sdw, sdw16, D_ * SI_);

    // ---- attention path ----
    rmsnorm_h_k<<<T_, 256>>>(hidden, ln1, nullptr, xnh);
    gemm_tc<0><<<dim3(24, 8), 256, GEMM_SMEM>>>(xnh, qkv, D_, nullptr, nullptr, nullptr);
    rope_conv_k<<<dim3(T_, H_ + 2 * KVH_), HD_>>>(q, k, v, pos_ids, qh, kh, vh);
    attn_mma_k<<<dim3(8, H_), 256, ATT_SMEM>>>(qh, kh, vh, aoh);
    gemm_tc<0><<<dim3(16, 8), 256, GEMM_SMEM>>>(aoh, oseg, D_, hidden, nullptr, nullptr);

    // ---- MoE path ----
    rmsnorm_h_k<<<T_, 256>>>(h, ln2, x2f, x2h);
    zero_cnt_k<<<1, 32>>>(cnt);
    router_k<<<T_, 256>>>(x2f, router_w, wslot, cnt, list);
    gemm_tc<1><<<dim3(22, 8, E_), 256, GEMM_SMEM>>>(x2h, egu, D_, nullptr, cnt, list);
    expert_act_k<<<dim3(CAP, E_), 256>>>(g, u, cnt, gah);
    gemm_tc<2><<<dim3(16, 8, E_), 256, GEMM_SMEM>>>(gah, edn, I_, nullptr, cnt, list);
    gemm_tc<0><<<dim3(88, 8), 256, GEMM_SMEM>>>(x2h, sgu, D_, nullptr, nullptr, nullptr);
    shared_act_k<<<T_, 256>>>(shg, shu, sah);
    gemm_tc<0><<<dim3(16, 8), 256, GEMM_SMEM>>>(sah, sdn, SI_, nullptr, nullptr, nullptr);
    sgate_k<<<T_, 256>>>(x2f, segw, sgate);
    combine_k<<<T_, 256>>>(h, moe, wslot, sgate, shd, out);
}

// round 16
// speedup vs baseline: 1.2578x; 1.0085x over previous
#include <cuda_runtime.h>
#include <cuda_fp16.h>
#include <math.h>
#include <stdint.h>

#define D_    2048
#define H_    16
#define KVH_  4
#define HD_   128
#define E_    8
#define I_    1408
#define SI_   5632
#define T_    1024
#define CAP   1024

typedef __half f16;

// ---------------- scratch (device globals; allocation-free) ----------------
__device__ float d_q[T_ * D_];
__device__ float d_k[T_ * KVH_ * HD_];
__device__ float d_v[T_ * KVH_ * HD_];
__device__ float d_h[T_ * D_];
__device__ float d_x2f[T_ * D_];
__device__ float d_g[E_ * CAP * I_];
__device__ float d_u[E_ * CAP * I_];
__device__ float d_moe[2 * T_ * D_];
__device__ float d_shg[T_ * SI_];
__device__ float d_shu[T_ * SI_];
__device__ float d_shd[T_ * D_];
__device__ float d_wslot[T_ * 2];
__device__ float d_sgate[T_];
__device__ int   d_cnt[E_];
__device__ int   d_list[E_ * CAP];
__device__ f16 d_qh[T_ * D_];
__device__ f16 d_kh[T_ * KVH_ * HD_];
__device__ f16 d_vh[T_ * KVH_ * HD_];
__device__ f16 d_xn_h[T_ * D_];
__device__ f16 d_x2_h[T_ * D_];
__device__ f16 d_ao_h[T_ * D_];
__device__ f16 d_ga_h[E_ * CAP * I_];
__device__ f16 d_sa_h[T_ * SI_];
// fp16 weights (converted once per launch)
__device__ f16 w_q16[D_ * D_];
__device__ f16 w_k16[KVH_*HD_ * D_];
__device__ f16 w_v16[KVH_*HD_ * D_];
__device__ f16 w_o16[D_ * D_];
__device__ f16 w_eg16[E_ * I_ * D_];
__device__ f16 w_eu16[E_ * I_ * D_];
__device__ f16 w_ed16[E_ * D_ * I_];
__device__ f16 w_sg16[SI_ * D_];
__device__ f16 w_su16[SI_ * D_];
__device__ f16 w_sd16[D_ * SI_];

// ---------------- PTX helpers ----------------
__device__ __forceinline__ unsigned sm_u32(const void* p) {
    return (unsigned)__cvta_generic_to_shared(p);
}
__device__ __forceinline__ void cp16(unsigned dst, const void* src) {
    asm volatile("cp.async.cg.shared.global [%0], [%1], 16;\n" :: "r"(dst), "l"(src));
}
__device__ __forceinline__ void cp16z(unsigned dst, const void* src, bool pred) {
    int sz = pred ? 16 : 0;
    asm volatile("cp.async.cg.shared.global [%0], [%1], 16, %2;\n" :: "r"(dst), "l"(src), "r"(sz));
}
__device__ __forceinline__ void cp_commit() { asm volatile("cp.async.commit_group;\n"); }
template<int N> __device__ __forceinline__ void cp_wait() {
    asm volatile("cp.async.wait_group %0;\n" :: "n"(N));
}
__device__ __forceinline__ void ldsm4(unsigned& r0, unsigned& r1, unsigned& r2, unsigned& r3, unsigned a) {
    asm volatile("ldmatrix.sync.aligned.m8n8.x4.shared.b16 {%0,%1,%2,%3}, [%4];\n"
                 : "=r"(r0), "=r"(r1), "=r"(r2), "=r"(r3) : "r"(a));
}
__device__ __forceinline__ void ldsm4t(unsigned& r0, unsigned& r1, unsigned& r2, unsigned& r3, unsigned a) {
    asm volatile("ldmatrix.sync.aligned.m8n8.x4.trans.shared.b16 {%0,%1,%2,%3}, [%4];\n"
                 : "=r"(r0), "=r"(r1), "=r"(r2), "=r"(r3) : "r"(a));
}
__device__ __forceinline__ void ldsm2(unsigned& r0, unsigned& r1, unsigned a) {
    asm volatile("ldmatrix.sync.aligned.m8n8.x2.shared.b16 {%0,%1}, [%2];\n"
                 : "=r"(r0), "=r"(r1) : "r"(a));
}
__device__ __forceinline__ void mma_f16(float* c, const unsigned* a, const unsigned* b) {
    asm volatile("mma.sync.aligned.m16n8k16.row.col.f32.f16.f16.f32 "
                 "{%0,%1,%2,%3}, {%4,%5,%6,%7}, {%8,%9}, {%0,%1,%2,%3};\n"
                 : "+f"(c[0]), "+f"(c[1]), "+f"(c[2]), "+f"(c[3])
                 : "r"(a[0]), "r"(a[1]), "r"(a[2]), "r"(a[3]), "r"(b[0]), "r"(b[1]));
}
__device__ __forceinline__ unsigned pack_h2(float a, float b) {
    __half2 t = __floats2half2_rn(a, b);
    return *(unsigned*)&t;
}

// ---------------- fused weight convert: all 10 matrices in one launch ----------------
struct WAll {
    const float* src[10];
    f16* dst[10];
    int end[10];   // prefix ends, units of 16 elements
};
__global__ void wconv_all_k(WAll wa, int total16) {
    int i = blockIdx.x * 256 + threadIdx.x;
    if (i >= total16) return;
    int j = 0;
#pragma unroll
    for (int t = 0; t < 9; t++) if (i >= wa.end[t]) j = t + 1;
    int base = (j == 0) ? 0 : wa.end[j - 1];
    size_t li = (size_t)(i - base);
    const float4* src = (const float4*)wa.src[j] + 4 * li;
    float4 a = src[0], b = src[1], c = src[2], d = src[3];
    __half2 hp[8];
    hp[0] = __floats2half2_rn(a.x, a.y); hp[1] = __floats2half2_rn(a.z, a.w);
    hp[2] = __floats2half2_rn(b.x, b.y); hp[3] = __floats2half2_rn(b.z, b.w);
    hp[4] = __floats2half2_rn(c.x, c.y); hp[5] = __floats2half2_rn(c.z, c.w);
    hp[6] = __floats2half2_rn(d.x, d.y); hp[7] = __floats2half2_rn(d.z, d.w);
    uint4* dst = (uint4*)wa.dst[j] + 2 * li;
    dst[0] = *(uint4*)&hp[0];
    dst[1] = *(uint4*)&hp[4];
}

// ---------------- segment descriptors for fused GEMM launches ----------------
struct Seg {
    const f16* W;
    const float* bias;
    float* C;
    int N;
    int tile0;
};
struct Segs {
    Seg s[3];
    int nseg;
};

// ---------------- fp16 x fp16 tensor-core GEMM ----------------
// 128x128x32 tiles, 256 threads (2x4 warps, 64x32 warp tile), 4-stage cp.async,
// 2 CTAs/SM. MODE 0: dense (M = T_). MODE 1: gather A rows via list.
// MODE 2: A linear in expert buf, scatter C rows.
#define GST 40
#define TILE_SB 10240                 // 128 rows * 80B fp16 (padded)
#define STAGE_B 20480                 // A + W
#define NSTAGE 4
#define GEMM_SMEM (NSTAGE * STAGE_B)  // 81920

template<int MODE>
__global__ __launch_bounds__(256, 2)
void gemm_tc(const f16* __restrict__ Ain, Segs segs, int K,
             const float* __restrict__ Res,
             const int* __restrict__ cnt, const int* __restrict__ list) {
    extern __shared__ __align__(16) char dynsm[];
    __shared__ int s_tok[128];
    int e = (MODE == 0) ? 0 : blockIdx.z;
    int rows = (MODE == 0) ? T_ : cnt[e];
    int m0 = blockIdx.y * 128;
    if (MODE != 0 && m0 >= rows) return;
    int nt = blockIdx.x;
    Seg sel = segs.s[0];
    if (segs.nseg > 1 && nt >= segs.s[1].tile0) sel = segs.s[1];
    if (segs.nseg > 2 && nt >= segs.s[2].tile0) sel = segs.s[2];
    int n0 = (nt - sel.tile0) * 128;
    int N = sel.N;
    int tid = threadIdx.x;

    const f16* B  = sel.W + (MODE ? (size_t)e * N * K : 0);
    const f16* Ah = Ain   + (MODE == 2 ? (size_t)e * CAP * K : 0);

    if (MODE != 0) {
        if (tid < 128) {
            int pos = m0 + tid;
            s_tok[tid] = (pos < rows) ? list[e * CAP + pos] : -1;
        }
        __syncthreads();
    }

    int nk = K / 32;
    auto load_stage = [&](int kt) {
        char* sb = dynsm + (kt % NSTAGE) * STAGE_B;
        f16* sA = (f16*)sb;
        f16* sB = (f16*)(sb + TILE_SB);
        int k0 = kt * 32;
#pragma unroll
        for (int p = 0; p < 2; p++) {
            int idx = tid + p * 256;
            int r = idx >> 2, c8 = (idx & 3) << 3;
            unsigned da = sm_u32(sA + r * GST + c8);
            if (MODE == 1) {
                int en = s_tok[r];
                bool pa = en >= 0;
                size_t ro = pa ? (size_t)(en >> 1) * K : 0;
                cp16z(da, Ain + ro + k0 + c8, pa);
            } else {
                cp16(da, Ah + (size_t)(m0 + r) * K + k0 + c8);
            }
            cp16(sm_u32(sB + r * GST + c8), B + (size_t)(n0 + r) * K + k0 + c8);
        }
        cp_commit();
    };

    int lane = tid & 31, warp = tid >> 5;
    int wm = warp & 1, wn = warp >> 1;
    unsigned offA = (lane & 15) * (GST * 2) + (lane >> 4) * 16;
    int l4 = lane & 15;
    unsigned offB = (l4 & 7) * (GST * 2) + ((l4 >> 3) & 1) * 16;

    float acc[4][4][4] = {};

    int npre = (nk < NSTAGE) ? nk : NSTAGE;
    for (int s = 0; s < npre; s++) load_stage(s);

    for (int kt = 0; kt < nk; kt++) {
        int rem = nk - 1 - kt;
        if (rem >= 3) cp_wait<3>();
        else if (rem == 2) cp_wait<2>();
        else if (rem == 1) cp_wait<1>();
        else cp_wait<0>();
        __syncthreads();
        char* sb = dynsm + (kt % NSTAGE) * STAGE_B;
        unsigned baseA = sm_u32(sb);
        unsigned baseB = baseA + TILE_SB;
#pragma unroll
        for (int ks = 0; ks < 2; ks++) {
            unsigned ah[4][4];
#pragma unroll
            for (int im = 0; im < 4; im++) {
                unsigned off = offA + (unsigned)((wm * 64 + im * 16) * (GST * 2) + ks * 32);
                ldsm4(ah[im][0], ah[im][1], ah[im][2], ah[im][3], baseA + off);
            }
#pragma unroll
            for (int in_ = 0; in_ < 4; in_++) {
                unsigned off = offB + (unsigned)((wn * 32 + in_ * 8) * (GST * 2) + ks * 32);
                unsigned bh[2];
                ldsm2(bh[0], bh[1], baseB + off);
#pragma unroll
                for (int im = 0; im < 4; im++) mma_f16(acc[im][in_], ah[im], bh);
            }
        }
        __syncthreads();
        if (kt + NSTAGE < nk) load_stage(kt + NSTAGE);
    }

    // ---- epilogue ----
#pragma unroll
    for (int im = 0; im < 4; im++) {
#pragma unroll
        for (int h2 = 0; h2 < 2; h2++) {
            int r = wm * 64 + im * 16 + (lane >> 2) + h2 * 8;
            int pos = m0 + r;
            size_t crow;
            if (MODE == 0) {
                crow = (size_t)pos;
            } else if (MODE == 1) {
                if (pos >= rows) continue;
                crow = (size_t)(e * CAP + pos);
            } else {
                if (pos >= rows) continue;
                int en = s_tok[r];
                crow = (size_t)((en & 1) * T_ + (en >> 1));
            }
#pragma unroll
            for (int in_ = 0; in_ < 4; in_++) {
                int cc = n0 + wn * 32 + in_ * 8 + (lane & 3) * 2;
                float v0 = acc[im][in_][h2 * 2 + 0];
                float v1 = acc[im][in_][h2 * 2 + 1];
                if (sel.bias) { v0 += sel.bias[cc]; v1 += sel.bias[cc + 1]; }
                if (MODE == 0 && Res) {
                    v0 += Res[(size_t)pos * N + cc];
                    v1 += Res[(size_t)pos * N + cc + 1];
                }
                sel.C[crow * N + cc]     = v0;
                sel.C[crow * N + cc + 1] = v1;
            }
        }
    }
}

// ---------------- RMSNorm + fp16 out ----------------
__global__ void rmsnorm_h_k(const float* __restrict__ x, const float* __restrict__ w,
                            float* __restrict__ yf, f16* __restrict__ hi) {
    int row = blockIdx.x;
    const float* xr = x + (size_t)row * D_;
    float s = 0.f;
    for (int i = threadIdx.x; i < D_; i += 256) { float v = xr[i]; s += v * v; }
    __shared__ float red[256];
    red[threadIdx.x] = s; __syncthreads();
    for (int st = 128; st > 0; st >>= 1) {
        if (threadIdx.x < st) red[threadIdx.x] += red[threadIdx.x + st];
        __syncthreads();
    }
    float inv = rsqrtf(red[0] / (float)D_ + 1e-6f);
    for (int i = threadIdx.x; i < D_; i += 256) {
        float v = w[i] * xr[i] * inv;
        size_t idx = (size_t)row * D_ + i;
        if (yf) yf[idx] = v;
        hi[idx] = __float2half_rn(v);
    }
}

// ---------------- RoPE + fp16 convert ----------------
__global__ void rope_conv_k(const float* __restrict__ q, const float* __restrict__ k,
                            const float* __restrict__ v, const int* __restrict__ pos_ids,
                            f16* __restrict__ qh, f16* __restrict__ kh,
                            f16* __restrict__ vh) {
    int s = blockIdx.x, hh = blockIdx.y, d = threadIdx.x;
    if (hh >= H_ + KVH_) {
        int kv = hh - H_ - KVH_;
        size_t i = ((size_t)s * KVH_ + kv) * HD_ + d;
        vh[i] = __float2half_rn(v[i]);
        return;
    }
    float pos = (float)pos_ids[s];
    int fi = d & 63;
    float ang = pos * exp2f(-0.31143075889f * (float)fi);
    float c = cosf(ang), sn = sinf(ang);
    const float* base; f16* dst;
    if (hh < H_) { size_t i = ((size_t)s * H_ + hh) * HD_; base = q + i; dst = qh + i; }
    else { size_t i = ((size_t)s * KVH_ + (hh - H_)) * HD_; base = k + i; dst = kh + i; }
    float vv = base[d];
    float vr = (d < 64) ? -base[d + 64] : base[d - 64];
    dst[d] = __float2half_rn(vv * c + vr * sn);
}

// ---------------- tensor-core flash attention ----------------
#define ATT_SMEM 104448
__global__ __launch_bounds__(256, 1)
void attn_mma_k(const f16* __restrict__ qh, const f16* __restrict__ kh,
                const f16* __restrict__ vh, f16* __restrict__ ohi) {
    extern __shared__ __align__(16) char sm[];
    f16* Qs = (f16*)sm;
    f16* Ksb[2] = {(f16*)(sm + 34816), (f16*)(sm + 52224)};
    f16* Vsb[2] = {(f16*)(sm + 69632), (f16*)(sm + 87040)};
    int qb = blockIdx.x, h = blockIdx.y, kvh = h >> 2;
    int tid = threadIdx.x, lane = tid & 31, warp = tid >> 5;

#pragma unroll
    for (int i = 0; i < 8; i++) {
        int chunk = tid + i * 256;
        int r = chunk >> 4, c = chunk & 15;
        cp16(sm_u32(Qs + r * 136 + c * 8),
             qh + (((size_t)(qb * 128 + r)) * H_ + h) * HD_ + c * 8);
    }
    cp_commit();
    int nkt = 2 * qb + 2;
    auto load_kv = [&](int kt) {
        int b = kt & 1;
#pragma unroll
        for (int i = 0; i < 4; i++) {
            int chunk = tid + i * 256;
            int r = chunk >> 4, c = chunk & 15;
            size_t gi = (((size_t)(kt * 64 + r)) * KVH_ + kvh) * HD_ + c * 8;
            cp16(sm_u32(Ksb[b] + r * 136 + c * 8), kh + gi);
            cp16(sm_u32(Vsb[b] + r * 136 + c * 8), vh + gi);
        }
        cp_commit();
    };
    load_kv(0);
    cp_wait<1>();
    __syncthreads();

    unsigned qf[8][4];
    {
        unsigned qbase = sm_u32(Qs + warp * 16 * 136);
        unsigned offA = (lane & 15) * 272 + (lane >> 4) * 16;
#pragma unroll
        for (int kc = 0; kc < 8; kc++)
            ldsm4(qf[kc][0], qf[kc][1], qf[kc][2], qf[kc][3], qbase + offA + kc * 32);
    }

    float oacc[16][4] = {};
    float mrow0 = -1e30f, mrow1 = -1e30f, lrow0 = 0.f, lrow1 = 0.f;
    const float scale = 0.08838834764831845f;
    int r0g = qb * 128 + warp * 16 + (lane >> 2);

    for (int kt = 0; kt < nkt; kt++) {
        if (kt + 1 < nkt) { load_kv(kt + 1); cp_wait<1>(); }
        else             { cp_wait<0>(); }
        __syncthreads();
        int b = kt & 1;
        unsigned kbase = sm_u32(Ksb[b]);
        unsigned vbase = sm_u32(Vsb[b]);
        float sacc[8][4] = {};
#pragma unroll
        for (int kc = 0; kc < 8; kc++) {
            unsigned kb[8][2];
#pragma unroll
            for (int np = 0; np < 4; np++) {
                unsigned r0, r1, r2, r3;
                ldsm4(r0, r1, r2, r3,
                      kbase + (unsigned)((np * 16 + (lane & 15)) * 272 + kc * 32 + (lane >> 4) * 16));
                kb[2*np][0] = r0; kb[2*np][1] = r2;
                kb[2*np+1][0] = r1; kb[2*np+1][1] = r3;
            }
#pragma unroll
            for (int n = 0; n < 8; n++) mma_f16(sacc[n], qf[kc], kb[n]);
        }
        bool domask = (kt >= 2 * qb);
#pragma unroll
        for (int n = 0; n < 8; n++) {
            int col = kt * 64 + n * 8 + (lane & 3) * 2;
#pragma unroll
            for (int j = 0; j < 4; j++) {
                float sv = sacc[n][j] * scale;
                if (domask && (col + (j & 1)) > (r0g + (j >> 1) * 8)) sv = -1e30f;
                sacc[n][j] = sv;
            }
        }
        float mx0 = -1e30f, mx1 = -1e30f;
#pragma unroll
        for (int n = 0; n < 8; n++) {
            mx0 = fmaxf(mx0, fmaxf(sacc[n][0], sacc[n][1]));
            mx1 = fmaxf(mx1, fmaxf(sacc[n][2], sacc[n][3]));
        }
        mx0 = fmaxf(mx0, __shfl_xor_sync(0xffffffffu, mx0, 1));
        mx0 = fmaxf(mx0, __shfl_xor_sync(0xffffffffu, mx0, 2));
        mx1 = fmaxf(mx1, __shfl_xor_sync(0xffffffffu, mx1, 1));
        mx1 = fmaxf(mx1, __shfl_xor_sync(0xffffffffu, mx1, 2));
        float mn0 = fmaxf(mrow0, mx0), mn1 = fmaxf(mrow1, mx1);
        float al0 = __expf(mrow0 - mn0), al1 = __expf(mrow1 - mn1);
        mrow0 = mn0; mrow1 = mn1;
        float ps0 = 0.f, ps1 = 0.f;
#pragma unroll
        for (int n = 0; n < 8; n++) {
            sacc[n][0] = __expf(sacc[n][0] - mn0);
            sacc[n][1] = __expf(sacc[n][1] - mn0);
            sacc[n][2] = __expf(sacc[n][2] - mn1);
            sacc[n][3] = __expf(sacc[n][3] - mn1);
            ps0 += sacc[n][0] + sacc[n][1];
            ps1 += sacc[n][2] + sacc[n][3];
        }
        ps0 += __shfl_xor_sync(0xffffffffu, ps0, 1);
        ps0 += __shfl_xor_sync(0xffffffffu, ps0, 2);
        ps1 += __shfl_xor_sync(0xffffffffu, ps1, 1);
        ps1 += __shfl_xor_sync(0xffffffffu, ps1, 2);
        lrow0 = lrow0 * al0 + ps0;
        lrow1 = lrow1 * al1 + ps1;
#pragma unroll
        for (int n = 0; n < 16; n++) {
            oacc[n][0] *= al0; oacc[n][1] *= al0;
            oacc[n][2] *= al1; oacc[n][3] *= al1;
        }
        unsigned pf[4][4];
#pragma unroll
        for (int kc2 = 0; kc2 < 4; kc2++) {
            pf[kc2][0] = pack_h2(sacc[2*kc2][0],   sacc[2*kc2][1]);
            pf[kc2][1] = pack_h2(sacc[2*kc2][2],   sacc[2*kc2][3]);
            pf[kc2][2] = pack_h2(sacc[2*kc2+1][0], sacc[2*kc2+1][1]);
            pf[kc2][3] = pack_h2(sacc[2*kc2+1][2], sacc[2*kc2+1][3]);
        }
#pragma unroll
        for (int kc2 = 0; kc2 < 4; kc2++) {
#pragma unroll
            for (int nd = 0; nd < 8; nd++) {
                unsigned r0, r1, r2, r3;
                ldsm4t(r0, r1, r2, r3,
                       vbase + (unsigned)((kc2 * 16 + (lane & 15)) * 272 + nd * 32 + (lane >> 4) * 16));
                unsigned b0[2] = {r0, r1}, b1[2] = {r2, r3};
                mma_f16(oacc[2*nd],     pf[kc2], b0);
                mma_f16(oacc[2*nd + 1], pf[kc2], b1);
            }
        }
        __syncthreads();
    }
    float inv0 = 1.f / lrow0, inv1 = 1.f / lrow1;
    size_t ob0 = (size_t)r0g * D_ + (size_t)h * HD_;
    size_t ob1 = (size_t)(r0g + 8) * D_ + (size_t)h * HD_;
#pragma unroll
    for (int n = 0; n < 16; n++) {
        int col = n * 8 + (lane & 3) * 2;
        *(__half2*)(ohi + ob0 + col) =
            __floats2half2_rn(oacc[n][0] * inv0, oacc[n][1] * inv0);
        *(__half2*)(ohi + ob1 + col) =
            __floats2half2_rn(oacc[n][2] * inv1, oacc[n][3] * inv1);
    }
}

// ---------------- router ----------------
__global__ void zero_cnt_k(int* cnt) { if (threadIdx.x < E_) cnt[threadIdx.x] = 0; }

__global__ void router_k(const float* __restrict__ x2, const float* __restrict__ rw,
                         float* __restrict__ wslot, int* __restrict__ cnt,
                         int* __restrict__ list) {
    int tok = blockIdx.x;
    int tid = threadIdx.x;
    int w = tid >> 5, lane = tid & 31;
    const float* xr = x2 + (size_t)tok * D_;
    const float* wr = rw + (size_t)w * D_;
    float s = 0.f;
    for (int i = lane; i < D_; i += 32) s += xr[i] * wr[i];
#pragma unroll
    for (int o = 16; o > 0; o >>= 1) s += __shfl_down_sync(0xffffffffu, s, o);
    __shared__ float lg[E_];
    if (lane == 0) lg[w] = s;
    __syncthreads();
    if (tid == 0) {
        float mx = lg[0];
        for (int e = 1; e < E_; e++) mx = fmaxf(mx, lg[e]);
        float p[E_]; float sum = 0.f;
        for (int e = 0; e < E_; e++) { p[e] = expf(lg[e] - mx); sum += p[e]; }
        for (int e = 0; e < E_; e++) p[e] /= sum;
        int i0 = 0;
        for (int e = 1; e < E_; e++) if (p[e] > p[i0]) i0 = e;
        int i1 = (i0 == 0) ? 1 : 0;
        for (int e = 0; e < E_; e++) if (e != i0 && p[e] > p[i1]) i1 = e;
        wslot[tok * 2 + 0] = p[i0];
        wslot[tok * 2 + 1] = p[i1];
        int pos0 = atomicAdd(&cnt[i0], 1); list[i0 * CAP + pos0] = tok * 2 + 0;
        int pos1 = atomicAdd(&cnt[i1], 1); list[i1 * CAP + pos1] = tok * 2 + 1;
    }
}

// ---------------- activations ----------------
__global__ void expert_act_k(const float* __restrict__ g, const float* __restrict__ u,
                             const int* __restrict__ cnt, f16* __restrict__ hi) {
    int e = blockIdx.y, pos = blockIdx.x;
    if (pos >= cnt[e]) return;
    size_t row = (size_t)(e * CAP + pos) * I_;
    for (int i = threadIdx.x; i < I_; i += 256) {
        float gv = g[row + i], uv = u[row + i];
        hi[row + i] = __float2half_rn(gv / (1.f + expf(-gv)) * uv);
    }
}

__global__ void shared_act_k(const float* __restrict__ g, const float* __restrict__ u,
                             f16* __restrict__ hi) {
    size_t row = (size_t)blockIdx.x * SI_;
    for (int i = threadIdx.x; i < SI_; i += 256) {
        float gv = g[row + i], uv = u[row + i];
        hi[row + i] = __float2half_rn(gv / (1.f + expf(-gv)) * uv);
    }
}

__global__ void sgate_k(const float* __restrict__ x2, const float* __restrict__ segw,
                        float* __restrict__ sg) {
    int tok = blockIdx.x; int tid = threadIdx.x;
    const float* xr = x2 + (size_t)tok * D_;
    float s = 0.f;
    for (int i = tid; i < D_; i += 256) s += xr[i] * segw[i];
    __shared__ float red[256];
    red[tid] = s; __syncthreads();
    for (int st = 128; st > 0; st >>= 1) {
        if (tid < st) red[tid] += red[tid + st];
        __syncthreads();
    }
    if (tid == 0) sg[tok] = 1.f / (1.f + expf(-red[0]));
}

__global__ void combine_k(const float* __restrict__ h, const float* __restrict__ moe,
                          const float* __restrict__ wslot, const float* __restrict__ sg,
                          const float* __restrict__ shd, float* __restrict__ out) {
    int tok = blockIdx.x; int tid = threadIdx.x;
    float w0 = wslot[tok * 2], w1 = wslot[tok * 2 + 1], gg = sg[tok];
    for (int d = tid; d < D_; d += 256) {
        size_t i = (size_t)tok * D_ + d;
        out[i] = h[i] + w0 * moe[i] + w1 * moe[(size_t)T_ * D_ + i] + gg * shd[i];
    }
}

// ---------------- launch ----------------
#define SYM(p, s) cudaGetSymbolAddress((void**)&p, s)

extern "C" void kernel_launch(void* const* d_in, const int* in_sizes, int n_in,
                              void* d_out, int out_size) {
    const float* hidden   = (const float*)d_in[0];
    const int*   pos_ids  = (const int*)d_in[1];
    const float* q_w      = (const float*)d_in[2];
    const float* q_b      = (const float*)d_in[3];
    const float* k_w      = (const float*)d_in[4];
    const float* k_b      = (const float*)d_in[5];
    const float* v_w      = (const float*)d_in[6];
    const float* v_b      = (const float*)d_in[7];
    const float* o_w      = (const float*)d_in[8];
    const float* ln1      = (const float*)d_in[9];
    const float* ln2      = (const float*)d_in[10];
    const float* router_w = (const float*)d_in[11];
    const float* eg       = (const float*)d_in[12];
    const float* eu       = (const float*)d_in[13];
    const float* ed       = (const float*)d_in[14];
    const float* sgw      = (const float*)d_in[15];
    const float* suw      = (const float*)d_in[16];
    const float* sdw      = (const float*)d_in[17];
    const float* segw     = (const float*)d_in[18];
    float* out = (float*)d_out;

    float *q, *k, *v, *h, *x2f, *g, *u, *moe, *shg, *shu, *shd, *wslot, *sgate;
    int *cnt, *list;
    SYM(q, d_q); SYM(k, d_k); SYM(v, d_v); SYM(h, d_h); SYM(x2f, d_x2f);
    SYM(g, d_g); SYM(u, d_u); SYM(moe, d_moe);
    SYM(shg, d_shg); SYM(shu, d_shu); SYM(shd, d_shd);
    SYM(wslot, d_wslot); SYM(sgate, d_sgate); SYM(cnt, d_cnt); SYM(list, d_list);
    f16 *qh, *kh, *vh, *xnh, *x2h, *aoh, *gah, *sah;
    SYM(qh, d_qh); SYM(kh, d_kh); SYM(vh, d_vh);
    SYM(xnh, d_xn_h); SYM(x2h, d_x2_h); SYM(aoh, d_ao_h);
    SYM(gah, d_ga_h); SYM(sah, d_sa_h);
    f16 *qw, *kw, *vw, *ow, *egw16, *euw16, *edw16, *sgw16, *suw16, *sdw16;
    SYM(qw, w_q16); SYM(kw, w_k16); SYM(vw, w_v16); SYM(ow, w_o16);
    SYM(egw16, w_eg16); SYM(euw16, w_eu16); SYM(edw16, w_ed16);
    SYM(sgw16, w_sg16); SYM(suw16, w_su16); SYM(sdw16, w_sd16);

    cudaFuncSetAttribute(gemm_tc<0>, cudaFuncAttributeMaxDynamicSharedMemorySize, GEMM_SMEM);
    cudaFuncSetAttribute(gemm_tc<1>, cudaFuncAttributeMaxDynamicSharedMemorySize, GEMM_SMEM);
    cudaFuncSetAttribute(gemm_tc<2>, cudaFuncAttributeMaxDynamicSharedMemorySize, GEMM_SMEM);
    cudaFuncSetAttribute(attn_mma_k, cudaFuncAttributeMaxDynamicSharedMemorySize, ATT_SMEM);

    Seg z = {nullptr, nullptr, nullptr, 0, 0};

    Segs qkv = {{{qw, q_b, q, D_, 0},
                 {kw, k_b, k, KVH_ * HD_, 16},
                 {vw, v_b, v, KVH_ * HD_, 20}}, 3};
    Segs oseg = {{{ow, nullptr, h, D_, 0}, z, z}, 1};
    Segs egu  = {{{egw16, nullptr, g, I_, 0},
                  {euw16, nullptr, u, I_, 11}, z}, 2};
    Segs edn  = {{{edw16, nullptr, moe, D_, 0}, z, z}, 1};
    Segs sgu  = {{{sgw16, nullptr, shg, SI_, 0},
                  {suw16, nullptr, shu, SI_, 44}, z}, 2};
    Segs sdn  = {{{sdw16, nullptr, shd, D_, 0}, z, z}, 1};

    // ---- fused weight conversion (one launch, all 10 matrices) ----
    {
        WAll wa;
        const float* srcs[10] = {q_w, k_w, v_w, o_w, eg, eu, ed, sgw, suw, sdw};
        f16* dsts[10] = {qw, kw, vw, ow, egw16, euw16, edw16, sgw16, suw16, sdw16};
        int ns[10] = {D_ * D_, KVH_ * HD_ * D_, KVH_ * HD_ * D_, D_ * D_,
                      E_ * I_ * D_, E_ * I_ * D_, E_ * D_ * I_,
                      SI_ * D_, SI_ * D_, D_ * SI_};
        int acc = 0;
        for (int i = 0; i < 10; i++) {
            wa.src[i] = srcs[i];
            wa.dst[i] = dsts[i];
            acc += ns[i] / 16;
            wa.end[i] = acc;
        }
        wconv_all_k<<<(acc + 255) / 256, 256>>>(wa, acc);
    }

    // ---- attention path ----
    rmsnorm_h_k<<<T_, 256>>>(hidden, ln1, nullptr, xnh);
    gemm_tc<0><<<dim3(24, 8), 256, GEMM_SMEM>>>(xnh, qkv, D_, nullptr, nullptr, nullptr);
    rope_conv_k<<<dim3(T_, H_ + 2 * KVH_), HD_>>>(q, k, v, pos_ids, qh, kh, vh);
    attn_mma_k<<<dim3(8, H_), 256, ATT_SMEM>>>(qh, kh, vh, aoh);
    gemm_tc<0><<<dim3(16, 8), 256, GEMM_SMEM>>>(aoh, oseg, D_, hidden, nullptr, nullptr);

    // ---- MoE path ----
    rmsnorm_h_k<<<T_, 256>>>(h, ln2, x2f, x2h);
    zero_cnt_k<<<1, 32>>>(cnt);
    router_k<<<T_, 256>>>(x2f, router_w, wslot, cnt, list);
    gemm_tc<1><<<dim3(22, 8, E_), 256, GEMM_SMEM>>>(x2h, egu, D_, nullptr, cnt, list);
    expert_act_k<<<dim3(CAP, E_), 256>>>(g, u, cnt, gah);
    gemm_tc<2><<<dim3(16, 8, E_), 256, GEMM_SMEM>>>(gah, edn, I_, nullptr, cnt, list);
    gemm_tc<0><<<dim3(88, 8), 256, GEMM_SMEM>>>(x2h, sgu, D_, nullptr, nullptr, nullptr);
    shared_act_k<<<T_, 256>>>(shg, shu, sah);
    gemm_tc<0><<<dim3(16, 8), 256, GEMM_SMEM>>>(sah, sdn, SI_, nullptr, nullptr, nullptr);
    sgate_k<<<T_, 256>>>(x2f, segw, sgate);
    combine_k<<<T_, 256>>>(h, moe, wslot, sgate, shd, out);
}